// round 1
// baseline (speedup 1.0000x reference)
#include <cuda_runtime.h>
#include <math.h>
#include <stdint.h>

#define BB 256
#define TT 32
#define SS 128
#define II 256
#define HH 1024
#define OO 256
#define G4 4096

// ---------------- scratch (static device globals; no allocation) ------------
__device__ float d_Xg[(size_t)TT * BB * G4];   // [T][B][4H] precomputed input gates + biases
__device__ float d_gates[BB * G4];             // current step gates
__device__ float d_h[BB * HH];
__device__ float d_c[BB * HH];
__device__ float d_u[2 * BB * 2 * HH];         // double-buffered [ctx|h] for FC

// ---------------- shared memory union ---------------------------------------
struct SmemGemm { uint32_t As[128][36]; uint32_t Bs[128][36]; };
struct SmemAttn { float ctx[8][1024]; float scores[128]; float mw[8]; float lw[8]; };
union SmemU { SmemGemm g; SmemAttn a; };

// ---------------- tf32 helpers ----------------------------------------------
__device__ __forceinline__ uint32_t f2tf32(float x) {
    uint32_t r;
    asm("cvt.rna.tf32.f32 %0, %1;" : "=r"(r) : "f"(x));
    return r;
}

__device__ __forceinline__ void mma_tf32(float c[4], const uint32_t a[4], const uint32_t b[2]) {
    asm volatile(
        "mma.sync.aligned.m16n8k8.row.col.f32.tf32.tf32.f32 "
        "{%0,%1,%2,%3}, {%4,%5,%6,%7}, {%8,%9}, {%0,%1,%2,%3};"
        : "+f"(c[0]), "+f"(c[1]), "+f"(c[2]), "+f"(c[3])
        : "r"(a[0]), "r"(a[1]), "r"(a[2]), "r"(a[3]), "r"(b[0]), "r"(b[1]));
}

// ---------------- generic tf32 GEMM: C[m,n] = sum_k A[m,k]*W[n,k] + epilogue --
// MODE 0: precompute Xg  (A = shifted_target gathered, t==0 rows are zero; +b_ih+b_hh)
// MODE 1: gates          (A = h; + Xg[t] slice)
// MODE 2: fc             (A = u buffer; + b_fc; strided store into outs)
template <int MODE>
__device__ __forceinline__ void gemm_dev(
    int ctam, int ctan,
    const float* __restrict__ Ag,     // A base
    const float* __restrict__ Bg,     // weights base [N][K]
    const float* __restrict__ e1,     // bias1 / Xg slice / b_fc
    const float* __restrict__ e2,     // bias2 (b_hh) or null
    float* __restrict__ Cout,
    int K, SmemU* sm)
{
    const int tid = threadIdx.x;
    const int lane = tid & 31;
    const int wid = tid >> 5;
    const int wm = wid & 3;   // 4 warps over M (32 rows each)
    const int wn = wid >> 2;  // 2 warps over N (64 cols each)

    float acc[2][8][4];
#pragma unroll
    for (int i = 0; i < 2; ++i)
#pragma unroll
        for (int j = 0; j < 8; ++j)
#pragma unroll
            for (int k = 0; k < 4; ++k) acc[i][j][k] = 0.f;

    for (int kc = 0; kc < K; kc += 32) {
        // stage A + B tiles (128 x 32 each), converting to tf32
#pragma unroll
        for (int it = 0; it < 4; ++it) {
            int slot = it * 256 + tid;          // 0..1023
            int row = slot >> 3;                // 0..127
            int cc = (slot & 7) << 2;           // 0,4,..,28

            float4 va;
            if (MODE == 0) {
                int m = ctam * 128 + row;
                int t_ = m >> 8;
                int b_ = m & 255;
                if (t_ == 0) {
                    va = make_float4(0.f, 0.f, 0.f, 0.f);
                } else {
                    va = *(const float4*)(Ag + ((size_t)b_ * TT + t_) * II + kc + cc);
                }
            } else {
                va = *(const float4*)(Ag + (size_t)(ctam * 128 + row) * K + kc + cc);
            }
            uint32_t* pa = &sm->g.As[row][cc];
            pa[0] = f2tf32(va.x); pa[1] = f2tf32(va.y);
            pa[2] = f2tf32(va.z); pa[3] = f2tf32(va.w);

            float4 vb = *(const float4*)(Bg + (size_t)(ctan * 128 + row) * K + kc + cc);
            uint32_t* pb = &sm->g.Bs[row][cc];
            pb[0] = f2tf32(vb.x); pb[1] = f2tf32(vb.y);
            pb[2] = f2tf32(vb.z); pb[3] = f2tf32(vb.w);
        }
        __syncthreads();

        const int tg = lane & 3;
        const int gp = lane >> 2;
#pragma unroll
        for (int ks = 0; ks < 4; ++ks) {
            uint32_t a[2][4], b[8][2];
#pragma unroll
            for (int mt = 0; mt < 2; ++mt) {
                int r = wm * 32 + mt * 16 + gp;
                a[mt][0] = sm->g.As[r][ks * 8 + tg];
                a[mt][1] = sm->g.As[r + 8][ks * 8 + tg];
                a[mt][2] = sm->g.As[r][ks * 8 + tg + 4];
                a[mt][3] = sm->g.As[r + 8][ks * 8 + tg + 4];
            }
#pragma unroll
            for (int nt = 0; nt < 8; ++nt) {
                int n = wn * 64 + nt * 8 + gp;
                b[nt][0] = sm->g.Bs[n][ks * 8 + tg];
                b[nt][1] = sm->g.Bs[n][ks * 8 + tg + 4];
            }
#pragma unroll
            for (int mt = 0; mt < 2; ++mt)
#pragma unroll
                for (int nt = 0; nt < 8; ++nt)
                    mma_tf32(acc[mt][nt], a[mt], b[nt]);
        }
        __syncthreads();
    }

    // epilogue
    const int tg = lane & 3;
    const int gp = lane >> 2;
#pragma unroll
    for (int mt = 0; mt < 2; ++mt) {
#pragma unroll
        for (int nt = 0; nt < 8; ++nt) {
            int gm0 = ctam * 128 + wm * 32 + mt * 16 + gp;
            int gn = ctan * 128 + wn * 64 + nt * 8 + tg * 2;
#pragma unroll
            for (int half = 0; half < 2; ++half) {
                int gm = gm0 + half * 8;
                float v0 = acc[mt][nt][half * 2 + 0];
                float v1 = acc[mt][nt][half * 2 + 1];
                if (MODE == 0) {
                    v0 += e1[gn] + e2[gn];
                    v1 += e1[gn + 1] + e2[gn + 1];
                    *(float2*)(Cout + (size_t)gm * G4 + gn) = make_float2(v0, v1);
                } else if (MODE == 1) {
                    float2 xg = *(const float2*)(e1 + (size_t)gm * G4 + gn);
                    v0 += xg.x; v1 += xg.y;
                    *(float2*)(Cout + (size_t)gm * G4 + gn) = make_float2(v0, v1);
                } else {
                    v0 += e1[gn]; v1 += e1[gn + 1];
                    // outs row stride is T*O
                    *(float2*)(Cout + (size_t)gm * (TT * OO) + gn) = make_float2(v0, v1);
                }
            }
        }
    }
}

// ---------------- attention (one CTA per batch, single-pass online softmax) --
__device__ __forceinline__ void attn_dev(int b, int tatt, const float* __restrict__ enc,
                                         float* __restrict__ out, int par, SmemU* sm)
{
    const int tid = threadIdx.x;
    const int lane = tid & 31;
    const int w = tid >> 5;

    // lane holds k = i*32 + lane, i = 0..31
    float hreg[32];
    const float* hb = d_h + (size_t)b * HH;
#pragma unroll
    for (int i = 0; i < 32; ++i) hreg[i] = hb[i * 32 + lane];

    float m = -1e30f, l = 0.f;
    float ctx[32];
#pragma unroll
    for (int i = 0; i < 32; ++i) ctx[i] = 0.f;

    for (int j = 0; j < 16; ++j) {
        int s = w * 16 + j;
        const float* er = enc + ((size_t)b * SS + s) * HH;
        float e[32];
        float dot = 0.f;
#pragma unroll
        for (int i = 0; i < 32; ++i) {
            e[i] = er[i * 32 + lane];
            dot += hreg[i] * e[i];
        }
#pragma unroll
        for (int o = 16; o; o >>= 1) dot += __shfl_xor_sync(0xffffffffu, dot, o);
        if (lane == 0) sm->a.scores[s] = dot;

        float nm = fmaxf(m, dot);
        float al = __expf(m - nm);
        float p = __expf(dot - nm);
        l = l * al + p;
#pragma unroll
        for (int i = 0; i < 32; ++i) ctx[i] = ctx[i] * al + p * e[i];
        m = nm;
    }
    if (lane == 0) { sm->a.mw[w] = m; sm->a.lw[w] = l; }
    __syncthreads();

    float M = -1e30f;
#pragma unroll
    for (int i = 0; i < 8; ++i) M = fmaxf(M, sm->a.mw[i]);
    float L = 0.f;
#pragma unroll
    for (int i = 0; i < 8; ++i) L += sm->a.lw[i] * __expf(sm->a.mw[i] - M);

    float sc = __expf(m - M);
#pragma unroll
    for (int i = 0; i < 32; ++i) sm->a.ctx[w][i * 32 + lane] = ctx[i] * sc;
    __syncthreads();

    float* ubuf = d_u + (size_t)par * BB * 2 * HH;
    for (int kk = tid; kk < HH; kk += 256) {
        float sum = 0.f;
#pragma unroll
        for (int ww = 0; ww < 8; ++ww) sum += sm->a.ctx[ww][kk];
        ubuf[(size_t)b * 2 * HH + kk] = sum / L;
        ubuf[(size_t)b * 2 * HH + HH + kk] = hb[kk];
    }
    if (tid < SS) {
        float p = __expf(sm->a.scores[tid] - M) / L;
        out[(size_t)BB * TT * OO + (size_t)b * TT * SS + (size_t)tatt * SS + tid] = p;
    }
}

// ---------------- kernels ----------------------------------------------------
__global__ void k_init() {
    int g = blockIdx.x * 256 + threadIdx.x;  // 65536 float4s
    float4 z = make_float4(0.f, 0.f, 0.f, 0.f);
    ((float4*)d_h)[g] = z;
    ((float4*)d_c)[g] = z;
}

__global__ void __launch_bounds__(256) k_pre(const float* __restrict__ st,
                                             const float* __restrict__ Wih,
                                             const float* __restrict__ bih,
                                             const float* __restrict__ bhh) {
    __shared__ SmemU sm;
    int ctam = blockIdx.x >> 5;  // 64 M-tiles (M = T*B = 8192)
    int ctan = blockIdx.x & 31;  // 32 N-tiles
    gemm_dev<0>(ctam, ctan, st, Wih, bih, bhh, d_Xg, II, &sm);
}

__global__ void __launch_bounds__(256) kA(int t, int nG, int nA,
                                          const float* __restrict__ enc,
                                          const float* __restrict__ Whh,
                                          const float* __restrict__ Wfc,
                                          const float* __restrict__ bfc,
                                          float* __restrict__ out) {
    __shared__ SmemU sm;
    int bid = blockIdx.x;
    if (bid < nG) {
        // gates GEMM for step t: gates = Xg[t] + h @ Whh^T
        gemm_dev<1>(bid >> 5, bid & 31, d_h, Whh,
                    d_Xg + (size_t)t * BB * G4, nullptr, d_gates, HH, &sm);
    } else if (bid < nG + nA) {
        // attention for step t-1
        attn_dev(bid - nG, t - 1, enc, out, (t - 1) & 1, &sm);
    } else {
        // fc for step t-2: outs[:, t-2, :] = u @ Wfc^T + b_fc
        int f = bid - nG - nA;  // 0..3 (2x2 tiles of 128)
        int tfc = t - 2;
        gemm_dev<2>(f >> 1, f & 1,
                    d_u + (size_t)(tfc & 1) * BB * 2 * HH, Wfc, bfc, nullptr,
                    out + (size_t)tfc * OO, 2 * HH, &sm);
    }
}

__global__ void k_cell() {
    int gid = blockIdx.x * 256 + threadIdx.x;  // 65536 threads, one float4 each
    int b = gid >> 8;
    int q = gid & 255;
    size_t gb = (size_t)b * G4 + q * 4;
    float4 gi = *(const float4*)(d_gates + gb);
    float4 gf = *(const float4*)(d_gates + gb + HH);
    float4 gg = *(const float4*)(d_gates + gb + 2 * HH);
    float4 go = *(const float4*)(d_gates + gb + 3 * HH);
    size_t hb = (size_t)b * HH + q * 4;
    float4 c = *(const float4*)(d_c + hb);

#define SIG(x) (1.f / (1.f + __expf(-(x))))
    c.x = SIG(gf.x) * c.x + SIG(gi.x) * tanhf(gg.x);
    c.y = SIG(gf.y) * c.y + SIG(gi.y) * tanhf(gg.y);
    c.z = SIG(gf.z) * c.z + SIG(gi.z) * tanhf(gg.z);
    c.w = SIG(gf.w) * c.w + SIG(gi.w) * tanhf(gg.w);
    float4 h;
    h.x = SIG(go.x) * tanhf(c.x);
    h.y = SIG(go.y) * tanhf(c.y);
    h.z = SIG(go.z) * tanhf(c.z);
    h.w = SIG(go.w) * tanhf(c.w);
#undef SIG
    *(float4*)(d_c + hb) = c;
    *(float4*)(d_h + hb) = h;
}

// ---------------- launch ------------------------------------------------------
extern "C" void kernel_launch(void* const* d_in, const int* in_sizes, int n_in,
                              void* d_out, int out_size) {
    const float* st  = (const float*)d_in[0];   // [B,T,I]
    const float* enc = (const float*)d_in[1];   // [B,S,H]
    const float* Wih = (const float*)d_in[2];   // [4H,I]
    const float* Whh = (const float*)d_in[3];   // [4H,H]
    const float* bih = (const float*)d_in[4];
    const float* bhh = (const float*)d_in[5];
    const float* Wfc = (const float*)d_in[6];   // [O,2H]
    const float* bfc = (const float*)d_in[7];
    float* out = (float*)d_out;                 // [outs (B,T,O) | probs (B,T,S)]

    k_init<<<256, 256>>>();
    k_pre<<<2048, 256>>>(st, Wih, bih, bhh);

    for (int t = 0; t <= TT + 1; ++t) {
        int nG = (t < TT) ? 64 : 0;
        int nA = (t >= 1 && t <= TT) ? BB : 0;
        int nF = (t >= 2) ? 4 : 0;
        kA<<<nG + nA + nF, 256>>>(t, nG, nA, enc, Whh, Wfc, bfc, out);
        if (t < TT) k_cell<<<256, 256>>>();
    }
}

// round 2
// speedup vs baseline: 1.0066x; 1.0066x over previous
#include <cuda_runtime.h>
#include <math.h>
#include <stdint.h>

#define BB 256
#define TT 32
#define SS 128
#define II 256
#define HH 1024
#define OO 256
#define G4 4096

// ---------------- scratch (static device globals; no allocation) ------------
__device__ float d_Xg[(size_t)TT * BB * G4];   // [T][B][4H] precomputed input gates + biases
__device__ float d_gates[BB * G4];
__device__ float d_h[BB * HH];
__device__ float d_c[BB * HH];
__device__ float d_u[2 * BB * 2 * HH];         // double-buffered [ctx|h] for FC
__device__ uint32_t d_Wih_t[G4 * II];          // tf32 pre-converted weights
__device__ uint32_t d_Whh_t[(size_t)G4 * HH];
__device__ uint32_t d_Wfc_t[OO * 2 * HH];

// ---------------- helpers ----------------------------------------------------
__device__ __forceinline__ uint32_t f2tf32(float x) {
    uint32_t r;
    asm("cvt.rna.tf32.f32 %0, %1;" : "=r"(r) : "f"(x));
    return r;
}
__device__ __forceinline__ uint32_t cvta_s(const void* p) {
    return (uint32_t)__cvta_generic_to_shared(p);
}
#define CPASYNC16(sa, g) asm volatile("cp.async.cg.shared.global [%0], [%1], 16;" :: "r"(sa), "l"(g))
#define CPASYNC16Z(sa, g, sz) asm volatile("cp.async.cg.shared.global [%0], [%1], 16, %2;" :: "r"(sa), "l"(g), "r"(sz))
#define CPCOMMIT() asm volatile("cp.async.commit_group;")
#define CPWAIT(n) asm volatile("cp.async.wait_group %0;" :: "n"(n))

__device__ __forceinline__ void mma_tf32(float c[4], const uint32_t a[4], const uint32_t b[2]) {
    asm volatile(
        "mma.sync.aligned.m16n8k8.row.col.f32.tf32.tf32.f32 "
        "{%0,%1,%2,%3}, {%4,%5,%6,%7}, {%8,%9}, {%0,%1,%2,%3};"
        : "+f"(c[0]), "+f"(c[1]), "+f"(c[2]), "+f"(c[3])
        : "r"(a[0]), "r"(a[1]), "r"(a[2]), "r"(a[3]), "r"(b[0]), "r"(b[1]));
}

// ---------------- tf32 GEMM, cp.async double-buffered ------------------------
// smem layout in dyn: As fp32 [2][128][36] @0, Bs u32 [2][128][36] @36864
// MODE 0: precompute Xg (A = shifted_target gathered, t==0 zero; +bih+bhh)
// MODE 1: gates (A = h fp32; + Xg[t])
// MODE 2: fc (A = u fp32; + b_fc; strided store into outs)
template <int MODE>
__device__ __forceinline__ void gemm_dev(
    int ctam, int ctan,
    const float* __restrict__ Ag,
    const uint32_t* __restrict__ Bt,
    const float* __restrict__ e1,
    const float* __restrict__ e2,
    float* __restrict__ Cout,
    int K, char* dyn)
{
    float* As = (float*)dyn;                 // [2][128*36]
    uint32_t* Bs = (uint32_t*)(dyn + 36864); // [2][128*36]
    const int tid = threadIdx.x;
    const int lane = tid & 31;
    const int wid = tid >> 5;
    const int wm = wid & 3;
    const int wn = wid >> 2;
    const int tg = lane & 3;
    const int gp = lane >> 2;

    float acc[2][8][4];
#pragma unroll
    for (int i = 0; i < 2; ++i)
#pragma unroll
        for (int j = 0; j < 8; ++j)
#pragma unroll
            for (int k = 0; k < 4; ++k) acc[i][j][k] = 0.f;

    const int nc = K >> 5;

    // stage chunk kc into buffer buf
    auto stage = [&](int buf, int kc) {
#pragma unroll
        for (int it = 0; it < 4; ++it) {
            int slot = it * 256 + tid;
            int row = slot >> 3;
            int cc = (slot & 7) << 2;
            uint32_t sa = cvta_s(As + buf * 4608 + row * 36 + cc);
            if (MODE == 0) {
                int m = ctam * 128 + row;
                int t_ = m >> 8;
                int b_ = m & 255;
                const float* ga = (t_ == 0) ? Ag
                    : Ag + ((size_t)b_ * TT + t_) * II + kc + cc;
                int sz = (t_ == 0) ? 0 : 16;
                CPASYNC16Z(sa, ga, sz);
            } else {
                CPASYNC16(sa, Ag + (size_t)(ctam * 128 + row) * K + kc + cc);
            }
            uint32_t sb = cvta_s(Bs + buf * 4608 + row * 36 + cc);
            CPASYNC16(sb, Bt + (size_t)(ctan * 128 + row) * K + kc + cc);
        }
    };

    stage(0, 0);
    CPCOMMIT();
    for (int c = 0; c < nc; ++c) {
        if (c + 1 < nc) stage((c + 1) & 1, (c + 1) * 32);
        CPCOMMIT();
        CPWAIT(1);
        __syncthreads();
        const float* Af = As + (c & 1) * 4608;
        const uint32_t* Bf = Bs + (c & 1) * 4608;
#pragma unroll
        for (int ks = 0; ks < 4; ++ks) {
            uint32_t a[2][4], b[8][2];
#pragma unroll
            for (int mt = 0; mt < 2; ++mt) {
                int r = wm * 32 + mt * 16 + gp;
                a[mt][0] = f2tf32(Af[r * 36 + ks * 8 + tg]);
                a[mt][1] = f2tf32(Af[(r + 8) * 36 + ks * 8 + tg]);
                a[mt][2] = f2tf32(Af[r * 36 + ks * 8 + tg + 4]);
                a[mt][3] = f2tf32(Af[(r + 8) * 36 + ks * 8 + tg + 4]);
            }
#pragma unroll
            for (int nt = 0; nt < 8; ++nt) {
                int n = wn * 64 + nt * 8 + gp;
                b[nt][0] = Bf[n * 36 + ks * 8 + tg];
                b[nt][1] = Bf[n * 36 + ks * 8 + tg + 4];
            }
#pragma unroll
            for (int mt = 0; mt < 2; ++mt)
#pragma unroll
                for (int nt = 0; nt < 8; ++nt)
                    mma_tf32(acc[mt][nt], a[mt], b[nt]);
        }
        __syncthreads();
    }

    // epilogue
#pragma unroll
    for (int mt = 0; mt < 2; ++mt) {
#pragma unroll
        for (int nt = 0; nt < 8; ++nt) {
            int gm0 = ctam * 128 + wm * 32 + mt * 16 + gp;
            int gn = ctan * 128 + wn * 64 + nt * 8 + tg * 2;
#pragma unroll
            for (int half = 0; half < 2; ++half) {
                int gm = gm0 + half * 8;
                float v0 = acc[mt][nt][half * 2 + 0];
                float v1 = acc[mt][nt][half * 2 + 1];
                if (MODE == 0) {
                    v0 += e1[gn] + e2[gn];
                    v1 += e1[gn + 1] + e2[gn + 1];
                    *(float2*)(Cout + (size_t)gm * G4 + gn) = make_float2(v0, v1);
                } else if (MODE == 1) {
                    float2 xg = *(const float2*)(e1 + (size_t)gm * G4 + gn);
                    v0 += xg.x; v1 += xg.y;
                    *(float2*)(Cout + (size_t)gm * G4 + gn) = make_float2(v0, v1);
                } else {
                    v0 += e1[gn]; v1 += e1[gn + 1];
                    *(float2*)(Cout + (size_t)gm * (TT * OO) + gn) = make_float2(v0, v1);
                }
            }
        }
    }
}

// ---------------- attention: cp.async pipelined single-pass softmax ----------
// dyn smem: es[3][8][1024] floats (96 KB); reused as ctx_s[8][1024] at the end.
__device__ __forceinline__ void attn_dev(int b, int tatt, const float* __restrict__ enc,
                                         float* __restrict__ out, int par, char* dyn,
                                         float* s_scores, float* s_m, float* s_l)
{
    float* es = (float*)dyn;
    const int tid = threadIdx.x;
    const int lane = tid & 31;
    const int w = tid >> 5;

    const float* hb = d_h + (size_t)b * HH;
    float hreg[32];
#pragma unroll
    for (int i = 0; i < 32; ++i) hreg[i] = hb[i * 32 + lane];

    const float* encb = enc + (size_t)b * SS * HH;

    // prefetch rows 0..2 for this warp
#pragma unroll
    for (int p = 0; p < 3; ++p) {
        const float* g = encb + (size_t)(w * 16 + p) * HH;
        float* sb = es + ((size_t)(p % 3) * 8 + w) * 1024;
#pragma unroll
        for (int q = 0; q < 8; ++q)
            CPASYNC16(cvta_s(sb + q * 128 + lane * 4), g + q * 128 + lane * 4);
        CPCOMMIT();
    }

    float m = -1e30f, l = 0.f;
    float ctx[32];
#pragma unroll
    for (int i = 0; i < 32; ++i) ctx[i] = 0.f;

    for (int j = 0; j < 16; ++j) {
        CPWAIT(2);
        __syncwarp();
        const float* e = es + ((size_t)(j % 3) * 8 + w) * 1024;
        float dot = 0.f;
#pragma unroll
        for (int i = 0; i < 32; ++i) dot += hreg[i] * e[i * 32 + lane];
#pragma unroll
        for (int o = 16; o; o >>= 1) dot += __shfl_xor_sync(0xffffffffu, dot, o);
        if (lane == 0) s_scores[w * 16 + j] = dot;

        float nm = fmaxf(m, dot);
        float al = __expf(m - nm);
        float p = __expf(dot - nm);
        l = l * al + p;
#pragma unroll
        for (int i = 0; i < 32; ++i) ctx[i] = ctx[i] * al + p * e[i * 32 + lane];
        m = nm;
        __syncwarp();
        if (j + 3 < 16) {
            const float* g = encb + (size_t)(w * 16 + j + 3) * HH;
            float* sb = es + ((size_t)(j % 3) * 8 + w) * 1024;
#pragma unroll
            for (int q = 0; q < 8; ++q)
                CPASYNC16(cvta_s(sb + q * 128 + lane * 4), g + q * 128 + lane * 4);
        }
        CPCOMMIT();
    }
    CPWAIT(0);
    if (lane == 0) { s_m[w] = m; s_l[w] = l; }
    __syncthreads();

    // global max / sum
    float M = -1e30f;
#pragma unroll
    for (int i = 0; i < 8; ++i) M = fmaxf(M, s_m[i]);
    float L = 0.f;
#pragma unroll
    for (int i = 0; i < 8; ++i) L += s_l[i] * __expf(s_m[i] - M);

    float sc = __expf(m - M);
    float* cs = es + (size_t)w * 1024;
#pragma unroll
    for (int i = 0; i < 32; ++i) cs[i * 32 + lane] = ctx[i] * sc;
    __syncthreads();

    float* ubuf = d_u + (size_t)par * BB * 2 * HH;
    for (int kk = tid; kk < HH; kk += 256) {
        float sum = 0.f;
#pragma unroll
        for (int ww = 0; ww < 8; ++ww) sum += es[(size_t)ww * 1024 + kk];
        ubuf[(size_t)b * 2 * HH + kk] = sum / L;
        ubuf[(size_t)b * 2 * HH + HH + kk] = hb[kk];
    }
    if (tid < SS) {
        float p = __expf(s_scores[tid] - M) / L;
        out[(size_t)BB * TT * OO + (size_t)b * TT * SS + (size_t)tatt * SS + tid] = p;
    }
}

// ---------------- kernels -----------------------------------------------------
__global__ void k_init() {
    int g = blockIdx.x * 256 + threadIdx.x;
    float4 z = make_float4(0.f, 0.f, 0.f, 0.f);
    ((float4*)d_h)[g] = z;
    ((float4*)d_c)[g] = z;
}

__global__ void __launch_bounds__(256) k_convert(const float* __restrict__ Wih,
                                                 const float* __restrict__ Whh,
                                                 const float* __restrict__ Wfc) {
    int g = blockIdx.x * 256 + threadIdx.x;
    int stride = gridDim.x * 256;
    for (int i = g; i < G4 * II; i += stride) d_Wih_t[i] = f2tf32(Wih[i]);
    for (int i = g; i < G4 * HH; i += stride) d_Whh_t[i] = f2tf32(Whh[i]);
    for (int i = g; i < OO * 2 * HH; i += stride) d_Wfc_t[i] = f2tf32(Wfc[i]);
}

__global__ void __launch_bounds__(256, 2) k_pre(const float* __restrict__ st,
                                                const float* __restrict__ bih,
                                                const float* __restrict__ bhh) {
    extern __shared__ char dyn[];
    int ctam = blockIdx.x >> 5;
    int ctan = blockIdx.x & 31;
    gemm_dev<0>(ctam, ctan, st, d_Wih_t, bih, bhh, d_Xg, II, dyn);
}

__global__ void __launch_bounds__(256, 2) kA(int t, int nG, int nA,
                                             const float* __restrict__ enc,
                                             const float* __restrict__ bfc,
                                             float* __restrict__ out) {
    extern __shared__ char dyn[];
    __shared__ float s_scores[SS];
    __shared__ float s_m[8], s_l[8];
    int bid = blockIdx.x;
    if (bid < nG) {
        gemm_dev<1>(bid >> 5, bid & 31, d_h, d_Whh_t,
                    d_Xg + (size_t)t * BB * G4, nullptr, d_gates, HH, dyn);
    } else if (bid < nG + nA) {
        attn_dev(bid - nG, t - 1, enc, out, (t - 1) & 1, dyn, s_scores, s_m, s_l);
    } else {
        int f = bid - nG - nA;  // 0..3
        int tfc = t - 2;
        gemm_dev<2>(f >> 1, f & 1,
                    d_u + (size_t)(tfc & 1) * BB * 2 * HH, d_Wfc_t, bfc, nullptr,
                    out + (size_t)tfc * OO, 2 * HH, dyn);
    }
}

__global__ void k_cell() {
    int gid = blockIdx.x * 256 + threadIdx.x;
    int b = gid >> 8;
    int q = gid & 255;
    size_t gb = (size_t)b * G4 + q * 4;
    float4 gi = *(const float4*)(d_gates + gb);
    float4 gf = *(const float4*)(d_gates + gb + HH);
    float4 gg = *(const float4*)(d_gates + gb + 2 * HH);
    float4 go = *(const float4*)(d_gates + gb + 3 * HH);
    size_t hb = (size_t)b * HH + q * 4;
    float4 c = *(const float4*)(d_c + hb);
#define SIG(x) (1.f / (1.f + __expf(-(x))))
    c.x = SIG(gf.x) * c.x + SIG(gi.x) * tanhf(gg.x);
    c.y = SIG(gf.y) * c.y + SIG(gi.y) * tanhf(gg.y);
    c.z = SIG(gf.z) * c.z + SIG(gi.z) * tanhf(gg.z);
    c.w = SIG(gf.w) * c.w + SIG(gi.w) * tanhf(gg.w);
    float4 h;
    h.x = SIG(go.x) * tanhf(c.x);
    h.y = SIG(go.y) * tanhf(c.y);
    h.z = SIG(go.z) * tanhf(c.z);
    h.w = SIG(go.w) * tanhf(c.w);
#undef SIG
    *(float4*)(d_c + hb) = c;
    *(float4*)(d_h + hb) = h;
}

// ---------------- launch --------------------------------------------------------
extern "C" void kernel_launch(void* const* d_in, const int* in_sizes, int n_in,
                              void* d_out, int out_size) {
    const float* st  = (const float*)d_in[0];
    const float* enc = (const float*)d_in[1];
    const float* Wih = (const float*)d_in[2];
    const float* Whh = (const float*)d_in[3];
    const float* bih = (const float*)d_in[4];
    const float* bhh = (const float*)d_in[5];
    const float* Wfc = (const float*)d_in[6];
    const float* bfc = (const float*)d_in[7];
    float* out = (float*)d_out;

    static const int DYN_GEMM = 73728;
    static const int DYN_KA = 98304;
    cudaFuncSetAttribute(k_pre, cudaFuncAttributeMaxDynamicSharedMemorySize, DYN_GEMM);
    cudaFuncSetAttribute(kA, cudaFuncAttributeMaxDynamicSharedMemorySize, DYN_KA);

    k_init<<<256, 256>>>();                       // launch 0
    k_convert<<<592, 256>>>(Wih, Whh, Wfc);       // launch 1
    k_pre<<<2048, 256, DYN_GEMM>>>(st, bih, bhh); // launch 2

    // launches 3..: kA(0), k_cell, kA(1) <- ncu -s 5 captures a full kA
    for (int t = 0; t <= TT + 1; ++t) {
        int nG = (t < TT) ? 64 : 0;
        int nA = (t >= 1 && t <= TT) ? BB : 0;
        int nF = (t >= 2) ? 4 : 0;
        kA<<<nG + nA + nF, 256, DYN_KA>>>(t, nG, nA, enc, bfc, out);
        if (t < TT) k_cell<<<256, 256>>>();
    }
}

// round 3
// speedup vs baseline: 2.7080x; 2.6903x over previous
#include <cuda_runtime.h>
#include <math.h>
#include <stdint.h>

#define BB 256
#define TT 32
#define SS 128
#define II 256
#define HH 1024
#define OO 256
#define G4 4096

// ---------------- scratch (static device globals; no allocation) ------------
__device__ float d_Xg[(size_t)TT * BB * G4];   // [T][B][4H] input gates + biases
__device__ float d_h[2][BB * HH];              // double-buffered hidden state
__device__ float d_c[BB * HH];
__device__ float d_u[2][BB * 2 * HH];          // double-buffered [ctx|h] for FC
__device__ float d_fcp[2][4][BB * OO];         // split-K FC partials
__device__ uint32_t d_Wih_t[G4 * II];          // tf32 pre-converted weights
__device__ uint32_t d_Whh_t[(size_t)G4 * HH];
__device__ uint32_t d_Wfc_t[OO * 2 * HH];

// ---------------- helpers ----------------------------------------------------
__device__ __forceinline__ uint32_t f2tf32(float x) {
    uint32_t r;
    asm("cvt.rna.tf32.f32 %0, %1;" : "=r"(r) : "f"(x));
    return r;
}
__device__ __forceinline__ uint32_t cvta_s(const void* p) {
    return (uint32_t)__cvta_generic_to_shared(p);
}
#define CPASYNC16(sa, g) asm volatile("cp.async.cg.shared.global [%0], [%1], 16;" :: "r"(sa), "l"(g))
#define CPASYNC16Z(sa, g, sz) asm volatile("cp.async.cg.shared.global [%0], [%1], 16, %2;" :: "r"(sa), "l"(g), "r"(sz))
#define CPCOMMIT() asm volatile("cp.async.commit_group;")
#define CPWAIT(n) asm volatile("cp.async.wait_group %0;" :: "n"(n))

__device__ __forceinline__ void mma_tf32(float c[4], const uint32_t a[4], const uint32_t b[2]) {
    asm volatile(
        "mma.sync.aligned.m16n8k8.row.col.f32.tf32.tf32.f32 "
        "{%0,%1,%2,%3}, {%4,%5,%6,%7}, {%8,%9}, {%0,%1,%2,%3};"
        : "+f"(c[0]), "+f"(c[1]), "+f"(c[2]), "+f"(c[3])
        : "r"(a[0]), "r"(a[1]), "r"(a[2]), "r"(a[3]), "r"(b[0]), "r"(b[1]));
}

#define SIG(x) (1.f / (1.f + __expf(-(x))))

// ========== precompute GEMM (k_pre only): 128x128 tiles, depth-2 =============
__device__ __forceinline__ void gemm_pre(
    int ctam, int ctan,
    const float* __restrict__ Ag, const uint32_t* __restrict__ Bt,
    const float* __restrict__ e1, const float* __restrict__ e2,
    float* __restrict__ Cout, int K, char* dyn)
{
    float* As = (float*)dyn;
    uint32_t* Bs = (uint32_t*)(dyn + 36864);
    const int tid = threadIdx.x;
    const int lane = tid & 31;
    const int wid = tid >> 5;
    const int wm = wid & 3;
    const int wn = wid >> 2;
    const int tg = lane & 3;
    const int gp = lane >> 2;

    float acc[2][8][4];
#pragma unroll
    for (int i = 0; i < 2; ++i)
#pragma unroll
        for (int j = 0; j < 8; ++j)
#pragma unroll
            for (int k = 0; k < 4; ++k) acc[i][j][k] = 0.f;

    const int nc = K >> 5;
    auto stage = [&](int buf, int kc) {
#pragma unroll
        for (int it = 0; it < 4; ++it) {
            int slot = it * 256 + tid;
            int row = slot >> 3;
            int cc = (slot & 7) << 2;
            uint32_t sa = cvta_s(As + buf * 4608 + row * 36 + cc);
            int m = ctam * 128 + row;
            int t_ = m >> 8;
            int b_ = m & 255;
            const float* ga = (t_ == 0) ? Ag : Ag + ((size_t)b_ * TT + t_) * II + kc + cc;
            int sz = (t_ == 0) ? 0 : 16;
            CPASYNC16Z(sa, ga, sz);
            uint32_t sb = cvta_s(Bs + buf * 4608 + row * 36 + cc);
            CPASYNC16(sb, Bt + (size_t)(ctan * 128 + row) * K + kc + cc);
        }
    };

    stage(0, 0);
    CPCOMMIT();
    for (int c = 0; c < nc; ++c) {
        if (c + 1 < nc) stage((c + 1) & 1, (c + 1) * 32);
        CPCOMMIT();
        CPWAIT(1);
        __syncthreads();
        const float* Af = As + (c & 1) * 4608;
        const uint32_t* Bf = Bs + (c & 1) * 4608;
#pragma unroll
        for (int ks = 0; ks < 4; ++ks) {
            uint32_t a[2][4], b[8][2];
#pragma unroll
            for (int mt = 0; mt < 2; ++mt) {
                int r = wm * 32 + mt * 16 + gp;
                a[mt][0] = f2tf32(Af[r * 36 + ks * 8 + tg]);
                a[mt][1] = f2tf32(Af[(r + 8) * 36 + ks * 8 + tg]);
                a[mt][2] = f2tf32(Af[r * 36 + ks * 8 + tg + 4]);
                a[mt][3] = f2tf32(Af[(r + 8) * 36 + ks * 8 + tg + 4]);
            }
#pragma unroll
            for (int nt = 0; nt < 8; ++nt) {
                int n = wn * 64 + nt * 8 + gp;
                b[nt][0] = Bf[n * 36 + ks * 8 + tg];
                b[nt][1] = Bf[n * 36 + ks * 8 + tg + 4];
            }
#pragma unroll
            for (int mt = 0; mt < 2; ++mt)
#pragma unroll
                for (int nt = 0; nt < 8; ++nt)
                    mma_tf32(acc[mt][nt], a[mt], b[nt]);
        }
        __syncthreads();
    }
#pragma unroll
    for (int mt = 0; mt < 2; ++mt)
#pragma unroll
        for (int nt = 0; nt < 8; ++nt) {
            int gm0 = ctam * 128 + wm * 32 + mt * 16 + gp;
            int gn = ctan * 128 + wn * 64 + nt * 8 + tg * 2;
#pragma unroll
            for (int half = 0; half < 2; ++half) {
                int gm = gm0 + half * 8;
                float v0 = acc[mt][nt][half * 2 + 0] + e1[gn] + e2[gn];
                float v1 = acc[mt][nt][half * 2 + 1] + e1[gn + 1] + e2[gn + 1];
                *(float2*)(Cout + (size_t)gm * G4 + gn) = make_float2(v0, v1);
            }
        }
}

// ========== fused gates GEMM + LSTM cell ======================================
// Tile: 64 M x (4 gates x 32 hidden cols). grid 4 x 32 = 128 CTAs. depth-3.
// smem: As fp32 [3][64][36] @0 (27648), Bs u32 [3][128][36] @27648 (55296)
// epilogue reuse: ep fp32 [64][132] @0
__device__ __forceinline__ void gatescell_dev(
    int ctam, int ctan,
    const float* __restrict__ hA,      // h_{t-1}
    const float* __restrict__ Xg,      // d_Xg + t*BB*G4
    float* __restrict__ hOut,          // h_t buffer
    char* dyn)
{
    float* As = (float*)dyn;
    uint32_t* Bs = (uint32_t*)(dyn + 27648);
    const int tid = threadIdx.x;
    const int lane = tid & 31;
    const int wid = tid >> 5;
    const int wm = wid & 1;      // 2 M halves of 32 rows
    const int g = wid >> 1;      // warp owns one gate (0..3)
    const int tg = lane & 3;
    const int gp = lane >> 2;
    const int q0 = ctan * 32;
    const int m0 = ctam * 64;

    float acc[2][4][4];
#pragma unroll
    for (int i = 0; i < 2; ++i)
#pragma unroll
        for (int j = 0; j < 4; ++j)
#pragma unroll
            for (int k = 0; k < 4; ++k) acc[i][j][k] = 0.f;

    auto stage = [&](int buf, int kc) {
        // A: 64x32 fp32 -> 512 float4, 2/thread
#pragma unroll
        for (int it = 0; it < 2; ++it) {
            int slot = it * 256 + tid;
            int row = slot >> 3;
            int cc = (slot & 7) << 2;
            CPASYNC16(cvta_s(As + buf * 2304 + row * 36 + cc),
                      hA + (size_t)(m0 + row) * HH + kc + cc);
        }
        // B: 128x32 u32 -> 1024 float4, 4/thread; rows gather 4 gate blocks
#pragma unroll
        for (int it = 0; it < 4; ++it) {
            int slot = it * 256 + tid;
            int row = slot >> 3;               // 0..127
            int cc = (slot & 7) << 2;
            int wr = (row >> 5) * HH + q0 + (row & 31);
            CPASYNC16(cvta_s(Bs + buf * 4608 + row * 36 + cc),
                      d_Whh_t + (size_t)wr * HH + kc + cc);
        }
    };

    stage(0, 0); CPCOMMIT();
    stage(1, 32); CPCOMMIT();
    const int nc = HH >> 5;  // 32
    for (int c = 0; c < nc; ++c) {
        if (c + 2 < nc) stage((c + 2) % 3, (c + 2) * 32);
        CPCOMMIT();
        CPWAIT(2);
        __syncthreads();
        const float* Af = As + (c % 3) * 2304;
        const uint32_t* Bf = Bs + (c % 3) * 4608;
#pragma unroll
        for (int ks = 0; ks < 4; ++ks) {
            uint32_t a[2][4], b[4][2];
#pragma unroll
            for (int mt = 0; mt < 2; ++mt) {
                int r = wm * 32 + mt * 16 + gp;
                a[mt][0] = f2tf32(Af[r * 36 + ks * 8 + tg]);
                a[mt][1] = f2tf32(Af[(r + 8) * 36 + ks * 8 + tg]);
                a[mt][2] = f2tf32(Af[r * 36 + ks * 8 + tg + 4]);
                a[mt][3] = f2tf32(Af[(r + 8) * 36 + ks * 8 + tg + 4]);
            }
#pragma unroll
            for (int nt = 0; nt < 4; ++nt) {
                int n = g * 32 + nt * 8 + gp;
                b[nt][0] = Bf[n * 36 + ks * 8 + tg];
                b[nt][1] = Bf[n * 36 + ks * 8 + tg + 4];
            }
#pragma unroll
            for (int mt = 0; mt < 2; ++mt)
#pragma unroll
                for (int nt = 0; nt < 4; ++nt)
                    mma_tf32(acc[mt][nt], a[mt], b[nt]);
        }
        __syncthreads();
    }

    // gate exchange: ep[row 64][n 128], n = g*32 + qq, stride 132
    float* ep = (float*)dyn;
    __syncthreads();
#pragma unroll
    for (int mt = 0; mt < 2; ++mt)
#pragma unroll
        for (int nt = 0; nt < 4; ++nt) {
            int r0 = wm * 32 + mt * 16 + gp;
            int col = g * 32 + nt * 8 + tg * 2;
            *(float2*)(ep + r0 * 132 + col) = make_float2(acc[mt][nt][0], acc[mt][nt][1]);
            *(float2*)(ep + (r0 + 8) * 132 + col) = make_float2(acc[mt][nt][2], acc[mt][nt][3]);
        }
    __syncthreads();

    // cell: 2048 elems, 8 per thread
#pragma unroll
    for (int k = 0; k < 8; ++k) {
        int idx = k * 256 + tid;
        int row = idx >> 5;
        int qq = idx & 31;
        int b = m0 + row;
        int q = q0 + qq;
        size_t xb = (size_t)b * G4 + q;
        float vi = ep[row * 132 + qq]        + Xg[xb];
        float vf = ep[row * 132 + 32 + qq]   + Xg[xb + HH];
        float vg = ep[row * 132 + 64 + qq]   + Xg[xb + 2 * HH];
        float vo = ep[row * 132 + 96 + qq]   + Xg[xb + 3 * HH];
        size_t hb = (size_t)b * HH + q;
        float c_old = d_c[hb];
        float c_new = SIG(vf) * c_old + SIG(vi) * tanhf(vg);
        float h_new = SIG(vo) * tanhf(c_new);
        d_c[hb] = c_new;
        hOut[hb] = h_new;
    }
}

// ========== FC split-K partial GEMM ==========================================
// Tile 128M x 64N, K-slice 512 (16 chunks), depth-3. grid 2x4x4 = 32 CTAs.
// smem: Af fp32 [3][128][36] @0 (55296), Bf u32 [3][64][36] @55296 (27648)
__device__ __forceinline__ void fcpart_dev(
    int ctam, int ctan, int kslice,
    const float* __restrict__ u,       // [256][2048]
    float* __restrict__ part)          // d_fcp[par][kslice] : [256][256]
{
    extern __shared__ char dyn[];
    float* Af = (float*)dyn;
    uint32_t* Bf = (uint32_t*)(dyn + 55296);
    const int tid = threadIdx.x;
    const int lane = tid & 31;
    const int wid = tid >> 5;
    const int wm = wid & 3;
    const int wn = wid >> 2;
    const int tg = lane & 3;
    const int gp = lane >> 2;
    const int k0 = kslice * 512;

    float acc[2][4][4];
#pragma unroll
    for (int i = 0; i < 2; ++i)
#pragma unroll
        for (int j = 0; j < 4; ++j)
#pragma unroll
            for (int k = 0; k < 4; ++k) acc[i][j][k] = 0.f;

    auto stage = [&](int buf, int kc) {
#pragma unroll
        for (int it = 0; it < 4; ++it) {
            int slot = it * 256 + tid;
            int row = slot >> 3;
            int cc = (slot & 7) << 2;
            CPASYNC16(cvta_s(Af + buf * 4608 + row * 36 + cc),
                      u + (size_t)(ctam * 128 + row) * (2 * HH) + k0 + kc + cc);
        }
#pragma unroll
        for (int it = 0; it < 2; ++it) {
            int slot = it * 256 + tid;
            int row = slot >> 3;
            int cc = (slot & 7) << 2;
            CPASYNC16(cvta_s(Bf + buf * 2304 + row * 36 + cc),
                      d_Wfc_t + (size_t)(ctan * 64 + row) * (2 * HH) + k0 + kc + cc);
        }
    };

    stage(0, 0); CPCOMMIT();
    stage(1, 32); CPCOMMIT();
    const int nc = 16;
    for (int c = 0; c < nc; ++c) {
        if (c + 2 < nc) stage((c + 2) % 3, (c + 2) * 32);
        CPCOMMIT();
        CPWAIT(2);
        __syncthreads();
        const float* A = Af + (c % 3) * 4608;
        const uint32_t* B = Bf + (c % 3) * 2304;
#pragma unroll
        for (int kk = 0; kk < 4; ++kk) {
            uint32_t a[2][4], b[4][2];
#pragma unroll
            for (int mt = 0; mt < 2; ++mt) {
                int r = wm * 32 + mt * 16 + gp;
                a[mt][0] = f2tf32(A[r * 36 + kk * 8 + tg]);
                a[mt][1] = f2tf32(A[(r + 8) * 36 + kk * 8 + tg]);
                a[mt][2] = f2tf32(A[r * 36 + kk * 8 + tg + 4]);
                a[mt][3] = f2tf32(A[(r + 8) * 36 + kk * 8 + tg + 4]);
            }
#pragma unroll
            for (int nt = 0; nt < 4; ++nt) {
                int n = wn * 32 + nt * 8 + gp;
                b[nt][0] = B[n * 36 + kk * 8 + tg];
                b[nt][1] = B[n * 36 + kk * 8 + tg + 4];
            }
#pragma unroll
            for (int mt = 0; mt < 2; ++mt)
#pragma unroll
                for (int nt = 0; nt < 4; ++nt)
                    mma_tf32(acc[mt][nt], a[mt], b[nt]);
        }
        __syncthreads();
    }
#pragma unroll
    for (int mt = 0; mt < 2; ++mt)
#pragma unroll
        for (int nt = 0; nt < 4; ++nt) {
            int gm0 = ctam * 128 + wm * 32 + mt * 16 + gp;
            int gn = ctan * 64 + wn * 32 + nt * 8 + tg * 2;
            *(float2*)(part + (size_t)gm0 * OO + gn) =
                make_float2(acc[mt][nt][0], acc[mt][nt][1]);
            *(float2*)(part + (size_t)(gm0 + 8) * OO + gn) =
                make_float2(acc[mt][nt][2], acc[mt][nt][3]);
        }
}

// ========== attention (cp.async pipelined single-pass softmax) ================
__device__ __forceinline__ void attn_dev(int b, int tatt, const float* __restrict__ enc,
                                         const float* __restrict__ hcur,
                                         float* __restrict__ out, int par, char* dyn,
                                         float* s_scores, float* s_m, float* s_l)
{
    float* es = (float*)dyn;
    const int tid = threadIdx.x;
    const int lane = tid & 31;
    const int w = tid >> 5;

    const float* hb = hcur + (size_t)b * HH;
    float hreg[32];
#pragma unroll
    for (int i = 0; i < 32; ++i) hreg[i] = hb[i * 32 + lane];

    const float* encb = enc + (size_t)b * SS * HH;
#pragma unroll
    for (int p = 0; p < 3; ++p) {
        const float* gsrc = encb + (size_t)(w * 16 + p) * HH;
        float* sb = es + ((size_t)(p % 3) * 8 + w) * 1024;
#pragma unroll
        for (int q = 0; q < 8; ++q)
            CPASYNC16(cvta_s(sb + q * 128 + lane * 4), gsrc + q * 128 + lane * 4);
        CPCOMMIT();
    }

    float m = -1e30f, l = 0.f;
    float ctx[32];
#pragma unroll
    for (int i = 0; i < 32; ++i) ctx[i] = 0.f;

    for (int j = 0; j < 16; ++j) {
        CPWAIT(2);
        __syncwarp();
        const float* e = es + ((size_t)(j % 3) * 8 + w) * 1024;
        float dot = 0.f;
#pragma unroll
        for (int i = 0; i < 32; ++i) dot += hreg[i] * e[i * 32 + lane];
#pragma unroll
        for (int o = 16; o; o >>= 1) dot += __shfl_xor_sync(0xffffffffu, dot, o);
        if (lane == 0) s_scores[w * 16 + j] = dot;

        float nm = fmaxf(m, dot);
        float al = __expf(m - nm);
        float p = __expf(dot - nm);
        l = l * al + p;
#pragma unroll
        for (int i = 0; i < 32; ++i) ctx[i] = ctx[i] * al + p * e[i * 32 + lane];
        m = nm;
        __syncwarp();
        if (j + 3 < 16) {
            const float* gsrc = encb + (size_t)(w * 16 + j + 3) * HH;
            float* sb = es + ((size_t)(j % 3) * 8 + w) * 1024;
#pragma unroll
            for (int q = 0; q < 8; ++q)
                CPASYNC16(cvta_s(sb + q * 128 + lane * 4), gsrc + q * 128 + lane * 4);
        }
        CPCOMMIT();
    }
    CPWAIT(0);
    if (lane == 0) { s_m[w] = m; s_l[w] = l; }
    __syncthreads();

    float M = -1e30f;
#pragma unroll
    for (int i = 0; i < 8; ++i) M = fmaxf(M, s_m[i]);
    float L = 0.f;
#pragma unroll
    for (int i = 0; i < 8; ++i) L += s_l[i] * __expf(s_m[i] - M);

    float sc = __expf(m - M);
    float* cs = es + (size_t)w * 1024;
#pragma unroll
    for (int i = 0; i < 32; ++i) cs[i * 32 + lane] = ctx[i] * sc;
    __syncthreads();

    float* ubuf = d_u[par];
    for (int kk = tid; kk < HH; kk += 256) {
        float sum = 0.f;
#pragma unroll
        for (int ww = 0; ww < 8; ++ww) sum += es[(size_t)ww * 1024 + kk];
        ubuf[(size_t)b * 2 * HH + kk] = sum / L;
        ubuf[(size_t)b * 2 * HH + HH + kk] = hb[kk];
    }
    if (tid < SS) {
        float p = __expf(s_scores[tid] - M) / L;
        out[(size_t)BB * TT * OO + (size_t)b * TT * SS + (size_t)tatt * SS + tid] = p;
    }
}

// ---------------- kernels -----------------------------------------------------
__global__ void k_init() {
    int g = blockIdx.x * 256 + threadIdx.x;  // 65536 float4s per array
    float4 z = make_float4(0.f, 0.f, 0.f, 0.f);
    ((float4*)d_h[1])[g] = z;
    ((float4*)d_c)[g] = z;
}

__global__ void __launch_bounds__(256) k_convert(const float* __restrict__ Wih,
                                                 const float* __restrict__ Whh,
                                                 const float* __restrict__ Wfc) {
    int g = blockIdx.x * 256 + threadIdx.x;
    int stride = gridDim.x * 256;
    for (int i = g; i < G4 * II; i += stride) d_Wih_t[i] = f2tf32(Wih[i]);
    for (int i = g; i < G4 * HH; i += stride) d_Whh_t[i] = f2tf32(Whh[i]);
    for (int i = g; i < OO * 2 * HH; i += stride) d_Wfc_t[i] = f2tf32(Wfc[i]);
}

__global__ void __launch_bounds__(256, 2) k_pre(const float* __restrict__ st,
                                                const float* __restrict__ bih,
                                                const float* __restrict__ bhh) {
    extern __shared__ char dyn[];
    gemm_pre(blockIdx.x >> 5, blockIdx.x & 31, st, d_Wih_t, bih, bhh, d_Xg, II, dyn);
}

__global__ void __launch_bounds__(256, 2) kA(int t, int nG, int nA, int nP,
                                             const float* __restrict__ enc,
                                             const float* __restrict__ bfc,
                                             float* __restrict__ out) {
    extern __shared__ char dyn[];
    __shared__ float s_scores[SS];
    __shared__ float s_m[8], s_l[8];
    int bid = blockIdx.x;
    if (bid < nG) {
        // fused gates GEMM + cell for step t: reads h_{t-1}, writes h_t, c
        gatescell_dev(bid >> 5, bid & 31,
                      d_h[(t + 1) & 1], d_Xg + (size_t)t * BB * G4,
                      d_h[t & 1], dyn);
    } else if (bid < nG + nA) {
        // attention for step t-1
        int ta = t - 1;
        attn_dev(bid - nG, ta, enc, d_h[ta & 1], out, ta & 1, dyn, s_scores, s_m, s_l);
    } else if (bid < nG + nA + nP) {
        // FC split-K partials for step t-2
        int f = bid - nG - nA;     // 0..31
        int tfc = t - 2;
        int ks = f & 3;
        int ctan = (f >> 2) & 3;
        int ctam = f >> 4;
        fcpart_dev(ctam, ctan, ks, d_u[tfc & 1], d_fcp[tfc & 1][ks]);
    } else {
        // FC reduce for step t-3
        int tr = t - 3;
        const float* p0 = d_fcp[tr & 1][0];
        const float* p1 = d_fcp[tr & 1][1];
        const float* p2 = d_fcp[tr & 1][2];
        const float* p3 = d_fcp[tr & 1][3];
        int bidr = bid - nG - nA - nP;  // 0..15
        for (int e = bidr * 256 + threadIdx.x; e < BB * OO; e += 16 * 256) {
            int b = e >> 8;
            int o = e & 255;
            float v = p0[e] + p1[e] + p2[e] + p3[e] + bfc[o];
            out[(size_t)b * TT * OO + (size_t)tr * OO + o] = v;
        }
    }
}

// ---------------- launch --------------------------------------------------------
extern "C" void kernel_launch(void* const* d_in, const int* in_sizes, int n_in,
                              void* d_out, int out_size) {
    const float* st  = (const float*)d_in[0];
    const float* enc = (const float*)d_in[1];
    const float* Wih = (const float*)d_in[2];
    const float* Whh = (const float*)d_in[3];
    const float* bih = (const float*)d_in[4];
    const float* bhh = (const float*)d_in[5];
    const float* Wfc = (const float*)d_in[6];
    const float* bfc = (const float*)d_in[7];
    float* out = (float*)d_out;

    static const int DYN_GEMM = 73728;
    static const int DYN_KA = 98304;
    cudaFuncSetAttribute(k_pre, cudaFuncAttributeMaxDynamicSharedMemorySize, DYN_GEMM);
    cudaFuncSetAttribute(kA, cudaFuncAttributeMaxDynamicSharedMemorySize, DYN_KA);

    k_init<<<256, 256>>>();                       // 0
    k_convert<<<592, 256>>>(Wih, Whh, Wfc);       // 1
    k_pre<<<2048, 256, DYN_GEMM>>>(st, bih, bhh); // 2

    // 3: kA(0), 4: kA(1), 5: kA(2) <- ncu -s 5 profiles mixed gates+attn+fc
    for (int t = 0; t <= TT + 2; ++t) {
        int nG = (t < TT) ? 128 : 0;                     // gates+cell step t
        int nA = (t >= 1 && t <= TT) ? BB : 0;           // attention step t-1
        int nP = (t >= 2 && t <= TT + 1) ? 32 : 0;       // fc partials step t-2
        int nR = (t >= 3) ? 16 : 0;                      // fc reduce step t-3
        kA<<<nG + nA + nP + nR, 256, DYN_KA>>>(t, nG, nA, nP, enc, bfc, out);
    }
}